// round 9
// baseline (speedup 1.0000x reference)
#include <cuda_runtime.h>
#include <cuda_fp16.h>
#include <cstdint>

#define NB    8192
#define SH    136    // padded half stride (68 words -> conflict-free)
#define ZSTH  136    // padded half2 stride for zth pair-rows

// shared memory byte offsets (16B aligned)
#define OFF_XRAW   0        // 4*512*4 = 8192 (4-slot ring)
#define OFF_B1     8192     // 512
#define OFF_B2     8704     // 512
#define OFF_B3     9216     // 128
#define OFF_W3T    9344     // 32*136*2 = 8704
#define OFF_H1A    18048    // 128*136*2 = 34816  (W2 staged here in prologue)
#define OFF_H1B    52864    // 34816
#define OFF_H2A    87680    // 34816
#define OFF_H2B    122496   // 34816
#define OFF_ZTH    157312   // 2*16*136*4 = 17408
#define OFF_WSM    174720   // 512*17*4 = 34816 (FSPool weights, padded stride 17)
#define SMEM_BYTES 209536

#define NTHREADS 512   // 16 warps

__device__ __forceinline__ void mma16816(float* d, const uint32_t* a, const uint32_t* b) {
    asm volatile(
        "mma.sync.aligned.m16n8k16.row.col.f32.f16.f16.f32 "
        "{%0,%1,%2,%3},{%4,%5,%6,%7},{%8,%9},{%0,%1,%2,%3};\n"
        : "+f"(d[0]), "+f"(d[1]), "+f"(d[2]), "+f"(d[3])
        : "r"(a[0]), "r"(a[1]), "r"(a[2]), "r"(a[3]), "r"(b[0]), "r"(b[1]));
}

__device__ __forceinline__ void mma16808(float* d, const uint32_t* a, uint32_t b) {
    asm volatile(
        "mma.sync.aligned.m16n8k8.row.col.f32.f16.f16.f32 "
        "{%0,%1,%2,%3},{%4,%5},{%6},{%0,%1,%2,%3};\n"
        : "+f"(d[0]), "+f"(d[1]), "+f"(d[2]), "+f"(d[3])
        : "r"(a[0]), "r"(a[1]), "r"(b));
}

#define LDSM4(r, addr) \
    asm volatile("ldmatrix.sync.aligned.m8n8.x4.shared.b16 {%0,%1,%2,%3}, [%4];" \
                 : "=r"((r)[0]), "=r"((r)[1]), "=r"((r)[2]), "=r"((r)[3]) : "r"(addr))

#define STSM4(addr, r0, r1, r2, r3) \
    asm volatile("stmatrix.sync.aligned.m8n8.x4.shared.b16 [%0], {%1,%2,%3,%4};" \
                 :: "r"(addr), "r"(r0), "r"(r1), "r"(r2), "r"(r3))

__device__ __forceinline__ void cp16(void* s, const void* g) {
    uint32_t sa = (uint32_t)__cvta_generic_to_shared(s);
    asm volatile("cp.async.ca.shared.global [%0], [%1], 16;\n" :: "r"(sa), "l"(g));
}

__device__ __forceinline__ uint32_t packh2(float a, float b) {
    __half2 h = __floats2half2_rn(a, b);
    return *(uint32_t*)&h;
}

__device__ __forceinline__ uint32_t h2max(uint32_t a, uint32_t b) {
    __half2 r = __hmax2(*(__half2*)&a, *(__half2*)&b);
    return *(uint32_t*)&r;
}
__device__ __forceinline__ uint32_t h2min(uint32_t a, uint32_t b) {
    __half2 r = __hmin2(*(__half2*)&a, *(__half2*)&b);
    return *(uint32_t*)&r;
}

#define CEXH(a, b, dsc) do { uint32_t _hi = h2max(a, b), _lo = h2min(a, b); \
                             (a) = (dsc) ? _hi : _lo; (b) = (dsc) ? _lo : _hi; } while (0)

// bitonic head: k=2, k=4 (element e = 4*lane + j, descending overall)
__device__ __forceinline__ void sort_head(uint32_t (&v)[2][4], int lane) {
#pragma unroll
    for (int q = 0; q < 2; q++) { CEXH(v[q][0], v[q][1], true); CEXH(v[q][2], v[q][3], false); }
    const bool dsc = (lane & 1) == 0;
#pragma unroll
    for (int q = 0; q < 2; q++) { CEXH(v[q][0], v[q][2], dsc); CEXH(v[q][1], v[q][3], dsc); }
#pragma unroll
    for (int q = 0; q < 2; q++) { CEXH(v[q][0], v[q][1], dsc); CEXH(v[q][2], v[q][3], dsc); }
}

// one bitonic merge stage for segment length KK (8..128)
template<int KK>
__device__ __forceinline__ void sort_stage(uint32_t (&v)[2][4], int lane) {
    const bool dsc = (lane & (KK >> 2)) == 0;
#pragma unroll
    for (int d = KK >> 1; d >= 4; d >>= 1) {
        const bool keep = dsc == ((lane & (d >> 2)) == 0);
#pragma unroll
        for (int q = 0; q < 2; q++)
#pragma unroll
            for (int j = 0; j < 4; j++) {
                uint32_t pv = __shfl_xor_sync(0xffffffffu, v[q][j], d >> 2);
                v[q][j] = keep ? h2max(v[q][j], pv) : h2min(v[q][j], pv);
            }
    }
#pragma unroll
    for (int q = 0; q < 2; q++) { CEXH(v[q][0], v[q][2], dsc); CEXH(v[q][1], v[q][3], dsc); }
#pragma unroll
    for (int q = 0; q < 2; q++) { CEXH(v[q][0], v[q][1], dsc); CEXH(v[q][2], v[q][3], dsc); }
}

__global__ void __launch_bounds__(NTHREADS, 1)
enc_kernel(const float* __restrict__ x,  const float* __restrict__ W1,
           const float* __restrict__ b1, const float* __restrict__ W2,
           const float* __restrict__ b2, const float* __restrict__ W3,
           const float* __restrict__ b3, const float* __restrict__ pw,
           const float* __restrict__ eps, float* __restrict__ out) {
    extern __shared__ char smem[];
    float*    xraw  = (float*)(smem + OFF_XRAW);
    float*    b1s   = (float*)(smem + OFF_B1);
    float*    b2s   = (float*)(smem + OFF_B2);
    float*    b3s   = (float*)(smem + OFF_B3);
    __half*   W3t   = (__half*)(smem + OFF_W3T);
    uint32_t* zth   = (uint32_t*)(smem + OFF_ZTH);   // [2][16][ZSTH] half2
    float*    wsm   = (float*)(smem + OFF_WSM);      // [512][17] FSPool weights

    const int tid  = threadIdx.x;
    const int w    = tid >> 5;
    const int lane = tid & 31;
    const int g    = lane >> 2, t = lane & 3;
    const int grid = gridDim.x;

    // warp tiles (16 warps)
    const int wm12 = (w & 1) * 64, wn12 = (w >> 1) * 16;   // layers 1,2: 64x16
    const int wm3  = (w & 7) * 16, wn3  = (w >> 3) * 16;   // layer 3: 16x16
    const int wb   = w >> 3;                                // sort: batch of pair

    // ldmatrix / stmatrix lane address components
    const int mi    = lane >> 3;
    const int arow  = (mi & 1) * 8 + (lane & 7);
    const int acol  = (mi >> 1) * 8;

    const uint32_t smem_u32 = (uint32_t)__cvta_generic_to_shared(smem);
    const uint32_t aOff2 = ((wm12 + arow) * SH + acol) * 2;
    const uint32_t aOff3 = ((wm3  + arow) * SH + acol) * 2;
    const uint32_t sOff  = ((wm12 + arow) * SH + wn12 + acol) * 2;

    // ---------------- prologue ----------------
    __half* W2t = (__half*)(smem + OFF_H1A);  // stage W2 in h1A region
    for (int i = tid; i < 16384; i += NTHREADS) {   // W2t[n][k] = W2[k][n]
        int k = i >> 7, n = i & 127;
        W2t[n * SH + k] = __float2half(W2[i]);
    }
    for (int i = tid; i < 4096; i += NTHREADS) {    // W3t[n][k] = W3[k][n]
        int k = i >> 5, n = i & 31;
        W3t[n * SH + k] = __float2half(W3[i]);
    }
    if (tid < 128) { b1s[tid] = b1[tid]; b2s[tid] = b2[tid]; }
    if (tid < 32)  b3s[tid] = b3[tid];
    // FSPool weights -> padded smem (stride 17: conflict-free per-thread rows)
    {
        float* wrow = wsm + tid * 17;
#pragma unroll
        for (int q = 0; q < 2; q++) {
            int c0 = 4 * (w & 7) + 2 * q;
#pragma unroll
            for (int j = 0; j < 4; j++) {
                int pp = 4 * lane + j;
                float pos = (float)pp * (20.0f / 127.0f);
                int idx = (int)pos; if (idx > 20) idx = 20;
                float frac = pos - (float)idx;
                int idx2 = idx + 1; if (idx2 > 20) idx2 = 20;
                wrow[q * 8 + j]     = (1.0f - frac) * pw[c0 * 21 + idx]       + frac * pw[c0 * 21 + idx2];
                wrow[q * 8 + 4 + j] = (1.0f - frac) * pw[(c0 + 1) * 21 + idx] + frac * pw[(c0 + 1) * 21 + idx2];
            }
        }
    }
    __syncthreads();

    // persistent W2 fragments (32 regs/lane: N=16 tile)
    uint32_t bW2[2][16];
#pragma unroll
    for (int nt = 0; nt < 2; nt++) {
        const __half* bp = W2t + (wn12 + 8 * nt + g) * SH + 2 * t;
#pragma unroll
        for (int ks = 0; ks < 8; ks++) {
            bW2[nt][2 * ks]     = *(const uint32_t*)(bp + 16 * ks);
            bW2[nt][2 * ks + 1] = *(const uint32_t*)(bp + 16 * ks + 8);
        }
    }
    // persistent W1 fragments
    uint32_t bW1[2];
#pragma unroll
    for (int nt = 0; nt < 2; nt++) {
        int n = wn12 + 8 * nt + g;
        bW1[nt] = (t < 2) ? packh2(W1[(2 * t) * 128 + n], W1[(2 * t + 1) * 128 + n]) : 0u;
    }

    // ---- phase lambdas ----
    auto layer1 = [&](const float* xb, uint32_t h1Off) {
        float acc[32];
#pragma unroll
        for (int i = 0; i < 32; i++) acc[i] = 0.f;
        uint32_t a1[4][2];
#pragma unroll
        for (int ms = 0; ms < 4; ms++) {
            int row = wm12 + 16 * ms + g;
            if (t < 2) {
                float2 v0 = *(const float2*)&xb[row * 4 + 2 * t];
                float2 v1 = *(const float2*)&xb[(row + 8) * 4 + 2 * t];
                a1[ms][0] = packh2(v0.x, v0.y);
                a1[ms][1] = packh2(v1.x, v1.y);
            } else { a1[ms][0] = 0u; a1[ms][1] = 0u; }
        }
#pragma unroll
        for (int ms = 0; ms < 4; ms++)
#pragma unroll
            for (int nt = 0; nt < 2; nt++)
                mma16808(&acc[(ms * 2 + nt) * 4], a1[ms], bW1[nt]);
#pragma unroll
        for (int ms = 0; ms < 4; ms++) {
            int c0 = wn12 + 2 * t;
            float bb0 = b1s[c0], bb1 = b1s[c0 + 1];
            float bb2 = b1s[c0 + 8], bb3 = b1s[c0 + 9];
            float* aA = &acc[(ms * 2 + 0) * 4];
            float* aB = &acc[(ms * 2 + 1) * 4];
            uint32_t p0 = packh2(fmaxf(aA[0] + bb0, 0.f), fmaxf(aA[1] + bb1, 0.f));
            uint32_t p1 = packh2(fmaxf(aA[2] + bb0, 0.f), fmaxf(aA[3] + bb1, 0.f));
            uint32_t p2 = packh2(fmaxf(aB[0] + bb2, 0.f), fmaxf(aB[1] + bb3, 0.f));
            uint32_t p3 = packh2(fmaxf(aB[2] + bb2, 0.f), fmaxf(aB[3] + bb3, 0.f));
            STSM4(h1Off + sOff + (16 * ms * SH) * 2, p0, p1, p2, p3);
        }
    };

    auto layer2 = [&](uint32_t h1Off, uint32_t h2Off) {
        float acc[32];
#pragma unroll
        for (int i = 0; i < 32; i++) acc[i] = 0.f;
        const uint32_t aB2 = h1Off + aOff2;
#pragma unroll
        for (int ks = 0; ks < 8; ks++) {
            uint32_t af[4][4];
#pragma unroll
            for (int ms = 0; ms < 4; ms++)
                LDSM4(af[ms], aB2 + (16 * ms * SH + 16 * ks) * 2);
#pragma unroll
            for (int ms = 0; ms < 4; ms++)
#pragma unroll
                for (int nt = 0; nt < 2; nt++)
                    mma16816(&acc[(ms * 2 + nt) * 4], af[ms], &bW2[nt][2 * ks]);
        }
#pragma unroll
        for (int ms = 0; ms < 4; ms++) {
            int c0 = wn12 + 2 * t;
            float bb0 = b2s[c0], bb1 = b2s[c0 + 1];
            float bb2 = b2s[c0 + 8], bb3 = b2s[c0 + 9];
            float* aA = &acc[(ms * 2 + 0) * 4];
            float* aB = &acc[(ms * 2 + 1) * 4];
            uint32_t p0 = packh2(fmaxf(aA[0] + bb0, 0.f), fmaxf(aA[1] + bb1, 0.f));
            uint32_t p1 = packh2(fmaxf(aA[2] + bb0, 0.f), fmaxf(aA[3] + bb1, 0.f));
            uint32_t p2 = packh2(fmaxf(aB[0] + bb2, 0.f), fmaxf(aB[1] + bb3, 0.f));
            uint32_t p3 = packh2(fmaxf(aB[2] + bb2, 0.f), fmaxf(aB[3] + bb3, 0.f));
            STSM4(h2Off + sOff + (16 * ms * SH) * 2, p0, p1, p2, p3);
        }
    };

    auto layer3 = [&](uint32_t h2Off, uint32_t* ztp) {
        float acc3[8];
#pragma unroll
        for (int i = 0; i < 8; i++) acc3[i] = 0.f;
        const uint32_t aB3 = h2Off + aOff3;
#pragma unroll
        for (int ks = 0; ks < 8; ks++) {
            uint32_t a3[4], bf[2][2];
            LDSM4(a3, aB3 + (16 * ks) * 2);
#pragma unroll
            for (int nt = 0; nt < 2; nt++) {
                const __half* bp = W3t + (wn3 + 8 * nt + g) * SH + 16 * ks + 2 * t;
                bf[nt][0] = *(const uint32_t*)(bp);
                bf[nt][1] = *(const uint32_t*)(bp + 8);
            }
#pragma unroll
            for (int nt = 0; nt < 2; nt++)
                mma16816(&acc3[nt * 4], a3, bf[nt]);
        }
#pragma unroll
        for (int nt = 0; nt < 2; nt++) {
            int r  = wm3 + g;
            int c  = wn3 + 8 * nt + 2 * t;
            int cp = c >> 1;
            float* a = &acc3[nt * 4];
            float bb0 = b3s[c], bb1 = b3s[c + 1];
            ztp[cp * ZSTH + r]     = packh2(a[0] + bb0, a[1] + bb1);
            ztp[cp * ZSTH + r + 8] = packh2(a[2] + bb0, a[3] + bb1);
        }
    };

    // ---- deferred-sort state (previous pair) ----
    uint32_t v[2][4];
    int  pbA = 0, pbB = 0;
    bool pvB = false, have = false;

    // final sort stage + pool + output for the PREVIOUS pair
    auto sortP3 = [&](float pev) {
        sort_stage<128>(v, lane);
        const float* wrow = wsm + tid * 17;
        float s[4];
#pragma unroll
        for (int q = 0; q < 2; q++) {
            float slo = 0.f, shi = 0.f;
#pragma unroll
            for (int j = 0; j < 4; j++) {
                float2 f = __half22float2(*(__half2*)&v[q][j]);
                slo += f.x * wrow[q * 8 + j];
                shi += f.y * wrow[q * 8 + 4 + j];
            }
            s[2 * q] = slo; s[2 * q + 1] = shi;
        }
#pragma unroll
        for (int off = 16; off > 0; off >>= 1)
#pragma unroll
            for (int i = 0; i < 4; i++)
                s[i] += __shfl_xor_sync(0xffffffffu, s[i], off);
        if (lane < 2 && ((wb == 0) || pvB)) {
            const int bb = wb ? pbB : pbA;
            const int l  = 2 * (w & 7) + lane;
            float mu = s[2 * lane];
            float lv = s[2 * lane + 1];
            float sp = mu + pev * expf(0.5f * lv);
            out[(size_t)bb * 16 + l]                       = mu;
            out[(size_t)NB * 16 + (size_t)bb * 16 + l]     = lv;
            out[(size_t)2 * NB * 16 + (size_t)bb * 16 + l] = sp;
        }
    };
    auto load_pev = [&]() -> float {
        float pev = 0.f;
        if (lane < 2 && ((wb == 0) || pvB)) {
            int bb = wb ? pbB : pbA;
            pev = eps[(size_t)bb * 16 + 2 * (w & 7) + lane];
        }
        return pev;
    };

    // prologue prefetch: slots 0,1 <- first pair
    {
        int bA = blockIdx.x;
        int bB = bA + grid; if (bB >= NB) bB = blockIdx.x;
        if (tid < 128) cp16(xraw + tid * 4, x + (size_t)bA * 512 + tid * 4);
        asm volatile("cp.async.commit_group;\n");
        if (tid < 128) cp16(xraw + 512 + tid * 4, x + (size_t)bB * 512 + tid * 4);
        asm volatile("cp.async.commit_group;\n");
    }

    int p = 0;
    for (int b = blockIdx.x; b < NB; b += 2 * grid, p ^= 1) {
        const int bA = b, bB = b + grid;
        const bool vB = bB < NB;
        // prefetch next pair into other-parity slots
        {
            int nA = b + 2 * grid; if (nA >= NB) nA = blockIdx.x;
            int nB = b + 3 * grid; if (nB >= NB) nB = blockIdx.x;
            int np = p ^ 1;
            if (tid < 128) cp16(xraw + (2 * np) * 512 + tid * 4, x + (size_t)nA * 512 + tid * 4);
            asm volatile("cp.async.commit_group;\n");
            if (tid < 128) cp16(xraw + (2 * np + 1) * 512 + tid * 4, x + (size_t)nB * 512 + tid * 4);
            asm volatile("cp.async.commit_group;\n");
        }
        asm volatile("cp.async.wait_group 2;\n");

        // eps for the PREVIOUS pair (consumed by sortP3 later this iteration)
        float pev = have ? load_pev() : 0.f;
        __syncthreads();

        // ---- GEMM phases with deferred-sort chunks interleaved ----
        layer1(xraw + (2 * p) * 512, OFF_H1A + smem_u32);
        layer1(xraw + (2 * p + 1) * 512, OFF_H1B + smem_u32);
        if (have) { sort_head(v, lane); sort_stage<8>(v, lane); sort_stage<16>(v, lane); }
        __syncthreads();

        layer2(OFF_H1A + smem_u32, OFF_H2A + smem_u32);
        layer2(OFF_H1B + smem_u32, OFF_H2B + smem_u32);
        if (have) { sort_stage<32>(v, lane); sort_stage<64>(v, lane); }
        __syncthreads();

        layer3(OFF_H2A + smem_u32, zth);
        layer3(OFF_H2B + smem_u32, zth + 16 * ZSTH);
        if (have) sortP3(pev);
        __syncthreads();

        // load current pair's z into registers (sorted during NEXT iteration)
        {
            const int sr = wb * 16 + 2 * (w & 7);
            uint4 q0 = *(const uint4*)&zth[sr * ZSTH + 4 * lane];
            uint4 q1 = *(const uint4*)&zth[(sr + 1) * ZSTH + 4 * lane];
            v[0][0] = q0.x; v[0][1] = q0.y; v[0][2] = q0.z; v[0][3] = q0.w;
            v[1][0] = q1.x; v[1][1] = q1.y; v[1][2] = q1.z; v[1][3] = q1.w;
        }
        pbA = bA; pbB = bB; pvB = vB; have = true;
        // next iter's zth writes are separated from this read by 3 barriers
    }

    // ---- epilogue: sort + output the final pair ----
    if (have) {
        float pev = load_pev();
        sort_head(v, lane); sort_stage<8>(v, lane); sort_stage<16>(v, lane);
        sort_stage<32>(v, lane); sort_stage<64>(v, lane);
        sortP3(pev);
    }
}

extern "C" void kernel_launch(void* const* d_in, const int* in_sizes, int n_in,
                              void* d_out, int out_size) {
    const float* x   = (const float*)d_in[0];
    const float* W1  = (const float*)d_in[1];
    const float* b1  = (const float*)d_in[2];
    const float* W2  = (const float*)d_in[3];
    const float* b2  = (const float*)d_in[4];
    const float* W3  = (const float*)d_in[5];
    const float* b3  = (const float*)d_in[6];
    const float* pw  = (const float*)d_in[7];
    const float* eps = (const float*)d_in[8];
    float* out = (float*)d_out;

    int dev = 0;
    cudaGetDevice(&dev);
    int nsm = 148;
    cudaDeviceGetAttribute(&nsm, cudaDevAttrMultiProcessorCount, dev);
    cudaFuncSetAttribute(enc_kernel, cudaFuncAttributeMaxDynamicSharedMemorySize, SMEM_BYTES);
    enc_kernel<<<nsm, NTHREADS, SMEM_BYTES>>>(x, W1, b1, W2, b2, W3, b3, pw, eps, out);
}

// round 10
// speedup vs baseline: 1.5510x; 1.5510x over previous
#include <cuda_runtime.h>
#include <cuda_fp16.h>
#include <cstdint>

#define NB    8192
#define SH    136    // padded half stride (68 words -> conflict-free)
#define ZSTH  136    // padded half2 stride for zth pair-rows

// shared memory byte offsets (16B aligned)
#define OFF_XRAW   0        // 4*512*4 = 8192 (4-slot ring)
#define OFF_B1     8192     // 512
#define OFF_B2     8704     // 512
#define OFF_B3     9216     // 128
#define OFF_W3T    9344     // 32*136*2 = 8704
#define OFF_H1A    18048    // 128*136*2 = 34816  (W2 staged here in prologue)
#define OFF_H1B    52864    // 34816
#define OFF_H2A    87680    // 34816
#define OFF_H2B    122496   // 34816
#define OFF_ZTH    157312   // 2 parities * (2*16*136*4) = 34816
#define SMEM_BYTES 192128

#define NTHREADS 512   // 16 warps

__device__ __forceinline__ void mma16816(float* d, const uint32_t* a, const uint32_t* b) {
    asm volatile(
        "mma.sync.aligned.m16n8k16.row.col.f32.f16.f16.f32 "
        "{%0,%1,%2,%3},{%4,%5,%6,%7},{%8,%9},{%0,%1,%2,%3};\n"
        : "+f"(d[0]), "+f"(d[1]), "+f"(d[2]), "+f"(d[3])
        : "r"(a[0]), "r"(a[1]), "r"(a[2]), "r"(a[3]), "r"(b[0]), "r"(b[1]));
}

__device__ __forceinline__ void mma16808(float* d, const uint32_t* a, uint32_t b) {
    asm volatile(
        "mma.sync.aligned.m16n8k8.row.col.f32.f16.f16.f32 "
        "{%0,%1,%2,%3},{%4,%5},{%6},{%0,%1,%2,%3};\n"
        : "+f"(d[0]), "+f"(d[1]), "+f"(d[2]), "+f"(d[3])
        : "r"(a[0]), "r"(a[1]), "r"(b));
}

#define LDSM4(r, addr) \
    asm volatile("ldmatrix.sync.aligned.m8n8.x4.shared.b16 {%0,%1,%2,%3}, [%4];" \
                 : "=r"((r)[0]), "=r"((r)[1]), "=r"((r)[2]), "=r"((r)[3]) : "r"(addr))

#define STSM4(addr, r0, r1, r2, r3) \
    asm volatile("stmatrix.sync.aligned.m8n8.x4.shared.b16 [%0], {%1,%2,%3,%4};" \
                 :: "r"(addr), "r"(r0), "r"(r1), "r"(r2), "r"(r3))

__device__ __forceinline__ void cp16(void* s, const void* g) {
    uint32_t sa = (uint32_t)__cvta_generic_to_shared(s);
    asm volatile("cp.async.ca.shared.global [%0], [%1], 16;\n" :: "r"(sa), "l"(g));
}

__device__ __forceinline__ uint32_t packh2(float a, float b) {
    __half2 h = __floats2half2_rn(a, b);
    return *(uint32_t*)&h;
}

__device__ __forceinline__ uint32_t h2max(uint32_t a, uint32_t b) {
    __half2 r = __hmax2(*(__half2*)&a, *(__half2*)&b);
    return *(uint32_t*)&r;
}
__device__ __forceinline__ uint32_t h2min(uint32_t a, uint32_t b) {
    __half2 r = __hmin2(*(__half2*)&a, *(__half2*)&b);
    return *(uint32_t*)&r;
}

#define CEXH(a, b, dsc) do { uint32_t _hi = h2max(a, b), _lo = h2min(a, b); \
                             (a) = (dsc) ? _hi : _lo; (b) = (dsc) ? _lo : _hi; } while (0)

// bitonic head: k=2, k=4 (element e = 4*lane + j, descending overall)
__device__ __forceinline__ void sort_head(uint32_t (&v)[2][4], int lane) {
#pragma unroll
    for (int q = 0; q < 2; q++) { CEXH(v[q][0], v[q][1], true); CEXH(v[q][2], v[q][3], false); }
    const bool dsc = (lane & 1) == 0;
#pragma unroll
    for (int q = 0; q < 2; q++) { CEXH(v[q][0], v[q][2], dsc); CEXH(v[q][1], v[q][3], dsc); }
#pragma unroll
    for (int q = 0; q < 2; q++) { CEXH(v[q][0], v[q][1], dsc); CEXH(v[q][2], v[q][3], dsc); }
}

// one bitonic merge stage for segment length KK (8..128)
template<int KK>
__device__ __forceinline__ void sort_stage(uint32_t (&v)[2][4], int lane) {
    const bool dsc = (lane & (KK >> 2)) == 0;
#pragma unroll
    for (int d = KK >> 1; d >= 4; d >>= 1) {
        const bool keep = dsc == ((lane & (d >> 2)) == 0);
#pragma unroll
        for (int q = 0; q < 2; q++)
#pragma unroll
            for (int j = 0; j < 4; j++) {
                uint32_t pv = __shfl_xor_sync(0xffffffffu, v[q][j], d >> 2);
                v[q][j] = keep ? h2max(v[q][j], pv) : h2min(v[q][j], pv);
            }
    }
#pragma unroll
    for (int q = 0; q < 2; q++) { CEXH(v[q][0], v[q][2], dsc); CEXH(v[q][1], v[q][3], dsc); }
#pragma unroll
    for (int q = 0; q < 2; q++) { CEXH(v[q][0], v[q][1], dsc); CEXH(v[q][2], v[q][3], dsc); }
}

__global__ void __launch_bounds__(NTHREADS, 1)
enc_kernel(const float* __restrict__ x,  const float* __restrict__ W1,
           const float* __restrict__ b1, const float* __restrict__ W2,
           const float* __restrict__ b2, const float* __restrict__ W3,
           const float* __restrict__ b3, const float* __restrict__ pw,
           const float* __restrict__ eps, float* __restrict__ out) {
    extern __shared__ char smem[];
    float*    xraw  = (float*)(smem + OFF_XRAW);
    float*    b1s   = (float*)(smem + OFF_B1);
    float*    b2s   = (float*)(smem + OFF_B2);
    float*    b3s   = (float*)(smem + OFF_B3);
    __half*   W3t   = (__half*)(smem + OFF_W3T);
    uint32_t* zth   = (uint32_t*)(smem + OFF_ZTH);   // [2 par][2 batch][16][ZSTH] half2

    const int tid  = threadIdx.x;
    const int w    = tid >> 5;
    const int lane = tid & 31;
    const int g    = lane >> 2, t = lane & 3;
    const int grid = gridDim.x;

    // warp tiles (16 warps)
    const int wm12 = (w & 1) * 64, wn12 = (w >> 1) * 16;   // layers 1,2: 64x16
    const int wm3  = (w & 7) * 16, wn3  = (w >> 3) * 16;   // layer 3: 16x16
    const int wb   = w >> 3;                                // sort/output: batch of pair

    // ldmatrix / stmatrix lane address components
    const int mi    = lane >> 3;
    const int arow  = (mi & 1) * 8 + (lane & 7);
    const int acol  = (mi >> 1) * 8;

    const uint32_t smem_u32 = (uint32_t)__cvta_generic_to_shared(smem);
    const uint32_t aOff2 = ((wm12 + arow) * SH + acol) * 2;
    const uint32_t aOff3 = ((wm3  + arow) * SH + acol) * 2;
    const uint32_t sOff  = ((wm12 + arow) * SH + wn12 + acol) * 2;

    // ---------------- prologue ----------------
    __half* W2t = (__half*)(smem + OFF_H1A);  // stage W2 in h1A region
    for (int i = tid; i < 16384; i += NTHREADS) {   // W2t[n][k] = W2[k][n]
        int k = i >> 7, n = i & 127;
        W2t[n * SH + k] = __float2half(W2[i]);
    }
    for (int i = tid; i < 4096; i += NTHREADS) {    // W3t[n][k] = W3[k][n]
        int k = i >> 5, n = i & 31;
        W3t[n * SH + k] = __float2half(W3[i]);
    }
    if (tid < 128) { b1s[tid] = b1[tid]; b2s[tid] = b2[tid]; }
    if (tid < 32)  b3s[tid] = b3[tid];
    __syncthreads();

    // persistent W2 fragments (32 regs/lane: N=16 tile)
    uint32_t bW2[2][16];
#pragma unroll
    for (int nt = 0; nt < 2; nt++) {
        const __half* bp = W2t + (wn12 + 8 * nt + g) * SH + 2 * t;
#pragma unroll
        for (int ks = 0; ks < 8; ks++) {
            bW2[nt][2 * ks]     = *(const uint32_t*)(bp + 16 * ks);
            bW2[nt][2 * ks + 1] = *(const uint32_t*)(bp + 16 * ks + 8);
        }
    }
    // persistent W1 fragments
    uint32_t bW1[2];
#pragma unroll
    for (int nt = 0; nt < 2; nt++) {
        int n = wn12 + 8 * nt + g;
        bW1[nt] = (t < 2) ? packh2(W1[(2 * t) * 128 + n], W1[(2 * t + 1) * 128 + n]) : 0u;
    }
    // FSPool weights: warp sorts streams q=0,1 -> channels (4(w&7)+2q, +1)
    float wlo[2][4], whi[2][4];
#pragma unroll
    for (int q = 0; q < 2; q++) {
        int c0 = 4 * (w & 7) + 2 * q;
#pragma unroll
        for (int j = 0; j < 4; j++) {
            int pp = 4 * lane + j;
            float pos = (float)pp * (20.0f / 127.0f);
            int idx = (int)pos; if (idx > 20) idx = 20;
            float frac = pos - (float)idx;
            int idx2 = idx + 1; if (idx2 > 20) idx2 = 20;
            wlo[q][j] = (1.0f - frac) * pw[c0 * 21 + idx]       + frac * pw[c0 * 21 + idx2];
            whi[q][j] = (1.0f - frac) * pw[(c0 + 1) * 21 + idx] + frac * pw[(c0 + 1) * 21 + idx2];
        }
    }

    // ---- phase lambdas ----
    auto layer1 = [&](const float* xb, uint32_t h1Off) {
        float acc[32];
#pragma unroll
        for (int i = 0; i < 32; i++) acc[i] = 0.f;
        uint32_t a1[4][2];
#pragma unroll
        for (int ms = 0; ms < 4; ms++) {
            int row = wm12 + 16 * ms + g;
            if (t < 2) {
                float2 v0 = *(const float2*)&xb[row * 4 + 2 * t];
                float2 v1 = *(const float2*)&xb[(row + 8) * 4 + 2 * t];
                a1[ms][0] = packh2(v0.x, v0.y);
                a1[ms][1] = packh2(v1.x, v1.y);
            } else { a1[ms][0] = 0u; a1[ms][1] = 0u; }
        }
#pragma unroll
        for (int ms = 0; ms < 4; ms++)
#pragma unroll
            for (int nt = 0; nt < 2; nt++)
                mma16808(&acc[(ms * 2 + nt) * 4], a1[ms], bW1[nt]);
#pragma unroll
        for (int ms = 0; ms < 4; ms++) {
            int c0 = wn12 + 2 * t;
            float bb0 = b1s[c0], bb1 = b1s[c0 + 1];
            float bb2 = b1s[c0 + 8], bb3 = b1s[c0 + 9];
            float* aA = &acc[(ms * 2 + 0) * 4];
            float* aB = &acc[(ms * 2 + 1) * 4];
            uint32_t p0 = packh2(fmaxf(aA[0] + bb0, 0.f), fmaxf(aA[1] + bb1, 0.f));
            uint32_t p1 = packh2(fmaxf(aA[2] + bb0, 0.f), fmaxf(aA[3] + bb1, 0.f));
            uint32_t p2 = packh2(fmaxf(aB[0] + bb2, 0.f), fmaxf(aB[1] + bb3, 0.f));
            uint32_t p3 = packh2(fmaxf(aB[2] + bb2, 0.f), fmaxf(aB[3] + bb3, 0.f));
            STSM4(h1Off + sOff + (16 * ms * SH) * 2, p0, p1, p2, p3);
        }
    };

    auto layer2 = [&](uint32_t h1Off, uint32_t h2Off) {
        float acc[32];
#pragma unroll
        for (int i = 0; i < 32; i++) acc[i] = 0.f;
        const uint32_t aB2 = h1Off + aOff2;
#pragma unroll
        for (int ks = 0; ks < 8; ks++) {
            uint32_t af[4][4];
#pragma unroll
            for (int ms = 0; ms < 4; ms++)
                LDSM4(af[ms], aB2 + (16 * ms * SH + 16 * ks) * 2);
#pragma unroll
            for (int ms = 0; ms < 4; ms++)
#pragma unroll
                for (int nt = 0; nt < 2; nt++)
                    mma16816(&acc[(ms * 2 + nt) * 4], af[ms], &bW2[nt][2 * ks]);
        }
#pragma unroll
        for (int ms = 0; ms < 4; ms++) {
            int c0 = wn12 + 2 * t;
            float bb0 = b2s[c0], bb1 = b2s[c0 + 1];
            float bb2 = b2s[c0 + 8], bb3 = b2s[c0 + 9];
            float* aA = &acc[(ms * 2 + 0) * 4];
            float* aB = &acc[(ms * 2 + 1) * 4];
            uint32_t p0 = packh2(fmaxf(aA[0] + bb0, 0.f), fmaxf(aA[1] + bb1, 0.f));
            uint32_t p1 = packh2(fmaxf(aA[2] + bb0, 0.f), fmaxf(aA[3] + bb1, 0.f));
            uint32_t p2 = packh2(fmaxf(aB[0] + bb2, 0.f), fmaxf(aB[1] + bb3, 0.f));
            uint32_t p3 = packh2(fmaxf(aB[2] + bb2, 0.f), fmaxf(aB[3] + bb3, 0.f));
            STSM4(h2Off + sOff + (16 * ms * SH) * 2, p0, p1, p2, p3);
        }
    };

    auto layer3 = [&](uint32_t h2Off, uint32_t* ztp) {
        float acc3[8];
#pragma unroll
        for (int i = 0; i < 8; i++) acc3[i] = 0.f;
        const uint32_t aB3 = h2Off + aOff3;
#pragma unroll
        for (int ks = 0; ks < 8; ks++) {
            uint32_t a3[4], bf[2][2];
            LDSM4(a3, aB3 + (16 * ks) * 2);
#pragma unroll
            for (int nt = 0; nt < 2; nt++) {
                const __half* bp = W3t + (wn3 + 8 * nt + g) * SH + 16 * ks + 2 * t;
                bf[nt][0] = *(const uint32_t*)(bp);
                bf[nt][1] = *(const uint32_t*)(bp + 8);
            }
#pragma unroll
            for (int nt = 0; nt < 2; nt++)
                mma16816(&acc3[nt * 4], a3, bf[nt]);
        }
#pragma unroll
        for (int nt = 0; nt < 2; nt++) {
            int r  = wm3 + g;
            int c  = wn3 + 8 * nt + 2 * t;
            int cp = c >> 1;
            float* a = &acc3[nt * 4];
            float bb0 = b3s[c], bb1 = b3s[c + 1];
            ztp[cp * ZSTH + r]     = packh2(a[0] + bb0, a[1] + bb1);
            ztp[cp * ZSTH + r + 8] = packh2(a[2] + bb0, a[3] + bb1);
        }
    };

    // ---- sort chunk helpers (state staged in zth[pp]; regs chunk-local) ----
    const int srBase = wb * 16 + 2 * (w & 7);
    auto sort_load = [&](int pp, uint32_t (&v)[2][4]) {
        const uint32_t* ztp = zth + pp * (32 * ZSTH);
        uint4 q0 = *(const uint4*)&ztp[srBase * ZSTH + 4 * lane];
        uint4 q1 = *(const uint4*)&ztp[(srBase + 1) * ZSTH + 4 * lane];
        v[0][0] = q0.x; v[0][1] = q0.y; v[0][2] = q0.z; v[0][3] = q0.w;
        v[1][0] = q1.x; v[1][1] = q1.y; v[1][2] = q1.z; v[1][3] = q1.w;
    };
    auto sort_store = [&](int pp, uint32_t (&v)[2][4]) {
        uint32_t* ztp = zth + pp * (32 * ZSTH);
        *(uint4*)&ztp[srBase * ZSTH + 4 * lane]       = make_uint4(v[0][0], v[0][1], v[0][2], v[0][3]);
        *(uint4*)&ztp[(srBase + 1) * ZSTH + 4 * lane] = make_uint4(v[1][0], v[1][1], v[1][2], v[1][3]);
    };
    // final: stage128 + pool + output for the previous pair
    auto sort_final = [&](uint32_t (&v)[2][4], float pev, int pbA, int pbB, bool pvB) {
        sort_stage<128>(v, lane);
        float s[4];
#pragma unroll
        for (int q = 0; q < 2; q++) {
            float slo = 0.f, shi = 0.f;
#pragma unroll
            for (int j = 0; j < 4; j++) {
                float2 f = __half22float2(*(__half2*)&v[q][j]);
                slo += f.x * wlo[q][j];
                shi += f.y * whi[q][j];
            }
            s[2 * q] = slo; s[2 * q + 1] = shi;
        }
#pragma unroll
        for (int off = 16; off > 0; off >>= 1)
#pragma unroll
            for (int i = 0; i < 4; i++)
                s[i] += __shfl_xor_sync(0xffffffffu, s[i], off);
        if (lane < 2 && ((wb == 0) || pvB)) {
            const int bb = wb ? pbB : pbA;
            const int l  = 2 * (w & 7) + lane;
            float mu = s[2 * lane];
            float lv = s[2 * lane + 1];
            float sp = mu + pev * expf(0.5f * lv);
            out[(size_t)bb * 16 + l]                       = mu;
            out[(size_t)NB * 16 + (size_t)bb * 16 + l]     = lv;
            out[(size_t)2 * NB * 16 + (size_t)bb * 16 + l] = sp;
        }
    };

    // prologue prefetch: slots 0,1 <- first pair
    {
        int bA = blockIdx.x;
        int bB = bA + grid; if (bB >= NB) bB = blockIdx.x;
        if (tid < 128) cp16(xraw + tid * 4, x + (size_t)bA * 512 + tid * 4);
        asm volatile("cp.async.commit_group;\n");
        if (tid < 128) cp16(xraw + 512 + tid * 4, x + (size_t)bB * 512 + tid * 4);
        asm volatile("cp.async.commit_group;\n");
    }

    int p = 0;
    int pbA = 0, pbB = 0;
    bool pvB = false, have = false;

    for (int b = blockIdx.x; b < NB; b += 2 * grid, p ^= 1) {
        const int bA = b, bB = b + grid;
        const bool vB = bB < NB;
        const int pp = p ^ 1;   // parity of the PREVIOUS pair's z buffer
        // prefetch next pair into other-parity slots
        {
            int nA = b + 2 * grid; if (nA >= NB) nA = blockIdx.x;
            int nB = b + 3 * grid; if (nB >= NB) nB = blockIdx.x;
            if (tid < 128) cp16(xraw + (2 * pp) * 512 + tid * 4, x + (size_t)nA * 512 + tid * 4);
            asm volatile("cp.async.commit_group;\n");
            if (tid < 128) cp16(xraw + (2 * pp + 1) * 512 + tid * 4, x + (size_t)nB * 512 + tid * 4);
            asm volatile("cp.async.commit_group;\n");
        }
        asm volatile("cp.async.wait_group 2;\n");

        // eps for the PREVIOUS pair (consumed by sort_final later this iteration)
        float pev = 0.f;
        if (have && lane < 2 && ((wb == 0) || pvB)) {
            int bb = wb ? pbB : pbA;
            pev = eps[(size_t)bb * 16 + 2 * (w & 7) + lane];
        }
        __syncthreads();

        // ---- GEMM phases with deferred-sort chunks (SMEM-staged) interleaved ----
        layer1(xraw + (2 * p) * 512, OFF_H1A + smem_u32);
        layer1(xraw + (2 * p + 1) * 512, OFF_H1B + smem_u32);
        if (have) {
            uint32_t v[2][4];
            sort_load(pp, v);
            sort_head(v, lane); sort_stage<8>(v, lane); sort_stage<16>(v, lane);
            sort_store(pp, v);
        }
        __syncthreads();

        layer2(OFF_H1A + smem_u32, OFF_H2A + smem_u32);
        layer2(OFF_H1B + smem_u32, OFF_H2B + smem_u32);
        if (have) {
            uint32_t v[2][4];
            sort_load(pp, v);
            sort_stage<32>(v, lane); sort_stage<64>(v, lane);
            sort_store(pp, v);
        }
        __syncthreads();

        layer3(OFF_H2A + smem_u32, zth + p * (32 * ZSTH));
        layer3(OFF_H2B + smem_u32, zth + p * (32 * ZSTH) + 16 * ZSTH);
        if (have) {
            uint32_t v[2][4];
            sort_load(pp, v);
            sort_final(v, pev, pbA, pbB, pvB);
        }
        __syncthreads();

        pbA = bA; pbB = bB; pvB = vB; have = true;
    }

    // ---- epilogue: sort + output the final pair (its z is at parity p^1) ----
    if (have) {
        const int pp = p ^ 1;
        float pev = 0.f;
        if (lane < 2 && ((wb == 0) || pvB)) {
            int bb = wb ? pbB : pbA;
            pev = eps[(size_t)bb * 16 + 2 * (w & 7) + lane];
        }
        uint32_t v[2][4];
        sort_load(pp, v);
        sort_head(v, lane); sort_stage<8>(v, lane); sort_stage<16>(v, lane);
        sort_stage<32>(v, lane); sort_stage<64>(v, lane);
        sort_final(v, pev, pbA, pbB, pvB);
    }
}

extern "C" void kernel_launch(void* const* d_in, const int* in_sizes, int n_in,
                              void* d_out, int out_size) {
    const float* x   = (const float*)d_in[0];
    const float* W1  = (const float*)d_in[1];
    const float* b1  = (const float*)d_in[2];
    const float* W2  = (const float*)d_in[3];
    const float* b2  = (const float*)d_in[4];
    const float* W3  = (const float*)d_in[5];
    const float* b3  = (const float*)d_in[6];
    const float* pw  = (const float*)d_in[7];
    const float* eps = (const float*)d_in[8];
    float* out = (float*)d_out;

    int dev = 0;
    cudaGetDevice(&dev);
    int nsm = 148;
    cudaDeviceGetAttribute(&nsm, cudaDevAttrMultiProcessorCount, dev);
    cudaFuncSetAttribute(enc_kernel, cudaFuncAttributeMaxDynamicSharedMemorySize, SMEM_BYTES);
    enc_kernel<<<nsm, NTHREADS, SMEM_BYTES>>>(x, W1, b1, W2, b2, W3, b3, pw, eps, out);
}

// round 12
// speedup vs baseline: 1.6109x; 1.0387x over previous
#include <cuda_runtime.h>
#include <cuda_fp16.h>
#include <cstdint>

#define NB    8192
#define SH    136    // padded half stride (68 words -> conflict-free)
#define ZSTH  136    // padded half2 stride for zth pair-rows
#define NTHREADS 256

// ---- shared memory layout (per CTA, ~106KB -> 2 CTAs/SM) ----
#define OFF_XRAW 0        // 2*512*4 = 4096 (x ring, 2 slots)
#define OFF_B1   4096     // 512
#define OFF_B2   4608     // 512
#define OFF_B3   5120     // 128
#define OFF_WPL  5248     // 16*128*4 = 8192  (FSPool weights, mu channels)
#define OFF_WPH  13440    // 8192             (FSPool weights, logvar channels)
#define OFF_W3T  21632    // 32*136*2 = 8704
#define OFF_H1   30336    // 128*136*2 = 34816  (W2 staged here in prologue)
#define OFF_H2   65152    // 34816
#define OFF_ZTH  99968    // 16*136*4 = 8704
#define SMEM_BYTES 108672

__device__ __forceinline__ void mma16816(float* d, const uint32_t* a, const uint32_t* b) {
    asm volatile(
        "mma.sync.aligned.m16n8k16.row.col.f32.f16.f16.f32 "
        "{%0,%1,%2,%3},{%4,%5,%6,%7},{%8,%9},{%0,%1,%2,%3};\n"
        : "+f"(d[0]), "+f"(d[1]), "+f"(d[2]), "+f"(d[3])
        : "r"(a[0]), "r"(a[1]), "r"(a[2]), "r"(a[3]), "r"(b[0]), "r"(b[1]));
}

__device__ __forceinline__ void mma16808(float* d, const uint32_t* a, uint32_t b) {
    asm volatile(
        "mma.sync.aligned.m16n8k8.row.col.f32.f16.f16.f32 "
        "{%0,%1,%2,%3},{%4,%5},{%6},{%0,%1,%2,%3};\n"
        : "+f"(d[0]), "+f"(d[1]), "+f"(d[2]), "+f"(d[3])
        : "r"(a[0]), "r"(a[1]), "r"(b));
}

#define LDSM4(r, addr) \
    asm volatile("ldmatrix.sync.aligned.m8n8.x4.shared.b16 {%0,%1,%2,%3}, [%4];" \
                 : "=r"((r)[0]), "=r"((r)[1]), "=r"((r)[2]), "=r"((r)[3]) : "r"(addr))

#define STSM4(addr, r0, r1, r2, r3) \
    asm volatile("stmatrix.sync.aligned.m8n8.x4.shared.b16 [%0], {%1,%2,%3,%4};" \
                 :: "r"(addr), "r"(r0), "r"(r1), "r"(r2), "r"(r3))

__device__ __forceinline__ void cp16(void* s, const void* g) {
    uint32_t sa = (uint32_t)__cvta_generic_to_shared(s);
    asm volatile("cp.async.ca.shared.global [%0], [%1], 16;\n" :: "r"(sa), "l"(g));
}

__device__ __forceinline__ uint32_t packh2(float a, float b) {
    __half2 h = __floats2half2_rn(a, b);
    return *(uint32_t*)&h;
}
__device__ __forceinline__ uint32_t h2max(uint32_t a, uint32_t b) {
    __half2 r = __hmax2(*(__half2*)&a, *(__half2*)&b); return *(uint32_t*)&r;
}
__device__ __forceinline__ uint32_t h2min(uint32_t a, uint32_t b) {
    __half2 r = __hmin2(*(__half2*)&a, *(__half2*)&b); return *(uint32_t*)&r;
}
#define CEXH(a, b, dsc) do { uint32_t _hi = h2max(a, b), _lo = h2min(a, b); \
                             (a) = (dsc) ? _hi : _lo; (b) = (dsc) ? _lo : _hi; } while (0)

__global__ void __launch_bounds__(NTHREADS, 2)
enc_kernel(const float* __restrict__ x,  const float* __restrict__ W1,
           const float* __restrict__ b1, const float* __restrict__ W2,
           const float* __restrict__ b2, const float* __restrict__ W3,
           const float* __restrict__ b3, const float* __restrict__ pw,
           const float* __restrict__ eps, float* __restrict__ out) {
    extern __shared__ char smem[];
    float*    xraw = (float*)(smem + OFF_XRAW);
    float*    b1s  = (float*)(smem + OFF_B1);
    float*    b2s  = (float*)(smem + OFF_B2);
    float*    b3s  = (float*)(smem + OFF_B3);
    float*    wpl  = (float*)(smem + OFF_WPL);
    float*    wph  = (float*)(smem + OFF_WPH);
    __half*   W3t  = (__half*)(smem + OFF_W3T);
    uint32_t* zth  = (uint32_t*)(smem + OFF_ZTH);

    const int tid  = threadIdx.x;
    const int w    = tid >> 5;          // 0..7
    const int lane = tid & 31;
    const int g    = lane >> 2, t = lane & 3;
    const int grid = gridDim.x;

    // L1/L2: each warp computes ALL 128 rows x 16 cols (wn = 16w). L3: 32x16 tiles.
    const int wn   = w * 16;
    const int wm3  = (w & 3) * 32, wn3 = (w >> 2) * 16;

    const int mi    = lane >> 3;
    const int arow  = (mi & 1) * 8 + (lane & 7);
    const int acol  = (mi >> 1) * 8;

    const uint32_t smem_u32 = (uint32_t)__cvta_generic_to_shared(smem);
    const uint32_t aB2 = smem_u32 + OFF_H1 + (arow * SH + acol) * 2;
    const uint32_t aB3 = smem_u32 + OFF_H2 + ((wm3 + arow) * SH + acol) * 2;
    const uint32_t sB1 = smem_u32 + OFF_H1 + (arow * SH + wn + acol) * 2;
    const uint32_t sB2 = smem_u32 + OFF_H2 + (arow * SH + wn + acol) * 2;

    // ---------------- prologue ----------------
    __half* W2t = (__half*)(smem + OFF_H1);   // stage W2 in h1 region
    for (int i = tid; i < 16384; i += NTHREADS) {   // W2t[n][k] = W2[k][n]
        int k = i >> 7, n = i & 127;
        W2t[n * SH + k] = __float2half(W2[i]);
    }
    for (int i = tid; i < 4096; i += NTHREADS) {    // W3t[n][k] = W3[k][n]
        int k = i >> 5, n = i & 31;
        W3t[n * SH + k] = __float2half(W3[i]);
    }
    if (tid < 128) { b1s[tid] = b1[tid]; b2s[tid] = b2[tid]; }
    if (tid < 32)  b3s[tid] = b3[tid];
    // FSPool weights: per pair-row cp, rank r
    for (int i = tid; i < 2048; i += NTHREADS) {
        int cp = i >> 7, r = i & 127;
        float pos = (float)r * (20.0f / 127.0f);
        int idx = (int)pos; if (idx > 20) idx = 20;
        float frac = pos - (float)idx;
        int idx2 = idx + 1; if (idx2 > 20) idx2 = 20;
        wpl[i] = (1.0f - frac) * pw[(2 * cp) * 21 + idx]     + frac * pw[(2 * cp) * 21 + idx2];
        wph[i] = (1.0f - frac) * pw[(2 * cp + 1) * 21 + idx] + frac * pw[(2 * cp + 1) * 21 + idx2];
    }
    __syncthreads();

    // persistent W2 fragments (N=16 tile -> 32 regs/lane)
    uint32_t bW2[2][16];
#pragma unroll
    for (int nt = 0; nt < 2; nt++) {
        const __half* bp = W2t + (wn + 8 * nt + g) * SH + 2 * t;
#pragma unroll
        for (int ks = 0; ks < 8; ks++) {
            bW2[nt][2 * ks]     = *(const uint32_t*)(bp + 16 * ks);
            bW2[nt][2 * ks + 1] = *(const uint32_t*)(bp + 16 * ks + 8);
        }
    }
    uint32_t bW1[2];
#pragma unroll
    for (int nt = 0; nt < 2; nt++) {
        int n = wn + 8 * nt + g;
        bW1[nt] = (t < 2) ? packh2(W1[(2 * t) * 128 + n], W1[(2 * t + 1) * 128 + n]) : 0u;
    }

    // prologue prefetch: slot 0 <- first batch
    {
        int b0 = blockIdx.x >= NB ? 0 : blockIdx.x;
        if (tid < 128) cp16(xraw + tid * 4, x + (size_t)b0 * 512 + tid * 4);
    }
    asm volatile("cp.async.commit_group;\n");

    int buf = 0;
    for (int b = blockIdx.x; b < NB; b += grid, buf ^= 1) {
        int bn = b + grid; if (bn >= NB) bn = blockIdx.x;
        if (tid < 128) cp16(xraw + (buf ^ 1) * 512 + tid * 4, x + (size_t)bn * 512 + tid * 4);
        asm volatile("cp.async.commit_group;\n");
        asm volatile("cp.async.wait_group 1;\n");

        // eps prefetch (consumed at output)
        float ev = 0.f;
        if (lane < 2) ev = eps[(size_t)b * 16 + 2 * w + lane];
        __syncthreads();

        const float* xb = xraw + buf * 512;

        // ---- layer 1: h1 = relu(x @ W1 + b1); per-warp 128x16, per-ms liveness ----
        {
            const int c0 = wn + 2 * t;
            const float bb0 = b1s[c0], bb1 = b1s[c0 + 1];
            const float bb2 = b1s[c0 + 8], bb3 = b1s[c0 + 9];
#pragma unroll
            for (int ms = 0; ms < 8; ms++) {
                float acc[8];
#pragma unroll
                for (int i = 0; i < 8; i++) acc[i] = 0.f;
                uint32_t a1[2];
                int row = 16 * ms + g;
                if (t < 2) {
                    float2 v0 = *(const float2*)&xb[row * 4 + 2 * t];
                    float2 v1 = *(const float2*)&xb[(row + 8) * 4 + 2 * t];
                    a1[0] = packh2(v0.x, v0.y);
                    a1[1] = packh2(v1.x, v1.y);
                } else { a1[0] = 0u; a1[1] = 0u; }
                mma16808(&acc[0], a1, bW1[0]);
                mma16808(&acc[4], a1, bW1[1]);
                uint32_t p0 = packh2(fmaxf(acc[0] + bb0, 0.f), fmaxf(acc[1] + bb1, 0.f));
                uint32_t p1 = packh2(fmaxf(acc[2] + bb0, 0.f), fmaxf(acc[3] + bb1, 0.f));
                uint32_t p2 = packh2(fmaxf(acc[4] + bb2, 0.f), fmaxf(acc[5] + bb3, 0.f));
                uint32_t p3 = packh2(fmaxf(acc[6] + bb2, 0.f), fmaxf(acc[7] + bb3, 0.f));
                STSM4(sB1 + (16 * ms * SH) * 2, p0, p1, p2, p3);
            }
        }
        __syncthreads();

        // ---- layer 2: h2 = relu(h1 @ W2 + b2); per-warp 128x16, B in regs ----
        {
            float acc[64];
#pragma unroll
            for (int i = 0; i < 64; i++) acc[i] = 0.f;
            uint32_t af[2][4];
            LDSM4(af[0], aB2);
#pragma unroll
            for (int it = 0; it < 64; it++) {
                const int ks = it >> 3, ms = it & 7;
                if (it < 63) {
                    const int nx = it + 1, ks2 = nx >> 3, ms2 = nx & 7;
                    LDSM4(af[nx & 1], aB2 + (16 * ms2 * SH + 16 * ks2) * 2);
                }
                mma16816(&acc[ms * 8],     af[it & 1], &bW2[0][2 * ks]);
                mma16816(&acc[ms * 8 + 4], af[it & 1], &bW2[1][2 * ks]);
            }
            const int c0 = wn + 2 * t;
            const float bb0 = b2s[c0], bb1 = b2s[c0 + 1];
            const float bb2 = b2s[c0 + 8], bb3 = b2s[c0 + 9];
#pragma unroll
            for (int ms = 0; ms < 8; ms++) {
                float* aA = &acc[ms * 8];
                float* aB = &acc[ms * 8 + 4];
                uint32_t p0 = packh2(fmaxf(aA[0] + bb0, 0.f), fmaxf(aA[1] + bb1, 0.f));
                uint32_t p1 = packh2(fmaxf(aA[2] + bb0, 0.f), fmaxf(aA[3] + bb1, 0.f));
                uint32_t p2 = packh2(fmaxf(aB[0] + bb2, 0.f), fmaxf(aB[1] + bb3, 0.f));
                uint32_t p3 = packh2(fmaxf(aB[2] + bb2, 0.f), fmaxf(aB[3] + bb3, 0.f));
                STSM4(sB2 + (16 * ms * SH) * 2, p0, p1, p2, p3);
            }
        }
        __syncthreads();

        // ---- layer 3: z^T = h2 @ W3 + b3 -> zth (half2 channel pairs); 32x16 tiles ----
        {
            float acc3[16];
#pragma unroll
            for (int i = 0; i < 16; i++) acc3[i] = 0.f;
#pragma unroll
            for (int ks = 0; ks < 8; ks++) {
                uint32_t a3[2][4], bf[2][2];
                LDSM4(a3[0], aB3 + (16 * ks) * 2);
                LDSM4(a3[1], aB3 + (16 * SH + 16 * ks) * 2);
#pragma unroll
                for (int nt = 0; nt < 2; nt++) {
                    const __half* bp = W3t + (wn3 + 8 * nt + g) * SH + 16 * ks + 2 * t;
                    bf[nt][0] = *(const uint32_t*)(bp);
                    bf[nt][1] = *(const uint32_t*)(bp + 8);
                }
                mma16816(&acc3[0],  a3[0], bf[0]);
                mma16816(&acc3[4],  a3[0], bf[1]);
                mma16816(&acc3[8],  a3[1], bf[0]);
                mma16816(&acc3[12], a3[1], bf[1]);
            }
#pragma unroll
            for (int ms = 0; ms < 2; ms++)
#pragma unroll
                for (int nt = 0; nt < 2; nt++) {
                    int r  = wm3 + 16 * ms + g;
                    int c  = wn3 + 8 * nt + 2 * t;
                    int cp = c >> 1;
                    float* a = &acc3[(ms * 2 + nt) * 4];
                    float bb0 = b3s[c], bb1 = b3s[c + 1];
                    zth[cp * ZSTH + r]     = packh2(a[0] + bb0, a[1] + bb1);
                    zth[cp * ZSTH + r + 8] = packh2(a[2] + bb0, a[3] + bb1);
                }
        }
        __syncthreads();

        // ---- sort + pool + output: 2 half2 streams/warp (pair-rows 2w, 2w+1) ----
        {
            uint32_t v[2][4];
#pragma unroll
            for (int q = 0; q < 2; q++) {
                uint4 qd = *(const uint4*)&zth[(2 * w + q) * ZSTH + 4 * lane];
                v[q][0] = qd.x; v[q][1] = qd.y; v[q][2] = qd.z; v[q][3] = qd.w;
            }
            // k=2
#pragma unroll
            for (int q = 0; q < 2; q++) { CEXH(v[q][0], v[q][1], true); CEXH(v[q][2], v[q][3], false); }
            // k=4
            {
                const bool dsc = (lane & 1) == 0;
#pragma unroll
                for (int q = 0; q < 2; q++) { CEXH(v[q][0], v[q][2], dsc); CEXH(v[q][1], v[q][3], dsc); }
#pragma unroll
                for (int q = 0; q < 2; q++) { CEXH(v[q][0], v[q][1], dsc); CEXH(v[q][2], v[q][3], dsc); }
            }
            // k = 8..128
#pragma unroll
            for (int kk = 8; kk <= 128; kk <<= 1) {
                const bool dsc = (lane & (kk >> 2)) == 0;
#pragma unroll
                for (int d = kk >> 1; d >= 4; d >>= 1) {
                    const bool keep = dsc == ((lane & (d >> 2)) == 0);
#pragma unroll
                    for (int q = 0; q < 2; q++)
#pragma unroll
                        for (int j = 0; j < 4; j++) {
                            uint32_t pv = __shfl_xor_sync(0xffffffffu, v[q][j], d >> 2);
                            v[q][j] = keep ? h2max(v[q][j], pv) : h2min(v[q][j], pv);
                        }
                }
#pragma unroll
                for (int q = 0; q < 2; q++) { CEXH(v[q][0], v[q][2], dsc); CEXH(v[q][1], v[q][3], dsc); }
#pragma unroll
                for (int q = 0; q < 2; q++) { CEXH(v[q][0], v[q][1], dsc); CEXH(v[q][2], v[q][3], dsc); }
            }
            // weighted pool from SMEM weights (rank r = 4*lane+j)
            float s[4];
#pragma unroll
            for (int q = 0; q < 2; q++) {
                float4 wlv = *(const float4*)&wpl[(2 * w + q) * 128 + 4 * lane];
                float4 whv = *(const float4*)&wph[(2 * w + q) * 128 + 4 * lane];
                float2 f0 = __half22float2(*(__half2*)&v[q][0]);
                float2 f1 = __half22float2(*(__half2*)&v[q][1]);
                float2 f2 = __half22float2(*(__half2*)&v[q][2]);
                float2 f3 = __half22float2(*(__half2*)&v[q][3]);
                s[2 * q]     = f0.x * wlv.x + f1.x * wlv.y + f2.x * wlv.z + f3.x * wlv.w;
                s[2 * q + 1] = f0.y * whv.x + f1.y * whv.y + f2.y * whv.z + f3.y * whv.w;
            }
#pragma unroll
            for (int off = 16; off > 0; off >>= 1)
#pragma unroll
                for (int i = 0; i < 4; i++)
                    s[i] += __shfl_xor_sync(0xffffffffu, s[i], off);

            if (lane < 2) {
                const int l = 2 * w + lane;
                float mu = s[2 * lane];
                float lv = s[2 * lane + 1];
                float sp = mu + ev * expf(0.5f * lv);
                out[(size_t)b * 16 + l]                       = mu;
                out[(size_t)NB * 16 + (size_t)b * 16 + l]     = lv;
                out[(size_t)2 * NB * 16 + (size_t)b * 16 + l] = sp;
            }
        }
        // next iteration's zth writes are >=3 barriers after these reads
    }
}

extern "C" void kernel_launch(void* const* d_in, const int* in_sizes, int n_in,
                              void* d_out, int out_size) {
    const float* x   = (const float*)d_in[0];
    const float* W1  = (const float*)d_in[1];
    const float* b1  = (const float*)d_in[2];
    const float* W2  = (const float*)d_in[3];
    const float* b2  = (const float*)d_in[4];
    const float* W3  = (const float*)d_in[5];
    const float* b3  = (const float*)d_in[6];
    const float* pw  = (const float*)d_in[7];
    const float* eps = (const float*)d_in[8];
    float* out = (float*)d_out;

    int dev = 0;
    cudaGetDevice(&dev);
    int nsm = 148;
    cudaDeviceGetAttribute(&nsm, cudaDevAttrMultiProcessorCount, dev);
    cudaFuncSetAttribute(enc_kernel, cudaFuncAttributeMaxDynamicSharedMemorySize, SMEM_BYTES);
    enc_kernel<<<2 * nsm, NTHREADS, SMEM_BYTES>>>(x, W1, b1, W2, b2, W3, b3, pw, eps, out);
}